// round 12
// baseline (speedup 1.0000x reference)
#include <cuda_runtime.h>
#include <cstdint>

// MinimalRSNN: GLIF3 + AlphaPSC recurrent SNN — single fused launch.
//   CTAs 0..127   : persistent 1000-step scan (R4-exact inner math)
//   CTAs 128..2127: I_ext = x @ W_in^T tiles (R4-exact fp32 SGEMM)
//   launch_bounds(256,2) -> <=128 regs -> every SM co-hosts scan + gemm CTA,
//   so the GEMM streams I_ext while the scan consumes it. Scan gates its
//   I_ext prefetch on per-m-block ready counters (release/acquire).
//   Phase C: out = spike_rate @ W_out^T

#define T_STEPS 1000
#define BATCH   32
#define NI      512
#define NH      1024
#define NO      256

#define V_TH   (-45.0f)
#define V_RST  (-60.0f)
#define D_SYN  0.8187307530779818f
#define D_A0   0.9048374180359595f
#define D_A1   0.8187307530779818f

#define NBLK   128
#define BM     128
#define BN     128
#define BK     8
#define MBLKS  ((T_STEPS * BATCH) / BM)   // 250
#define NTILES (NH / BN)                  // 8
#define GBLKS  (MBLKS * NTILES)           // 2000

#define FMA2(d, a, b)  asm("fma.rn.f32x2 %0, %1, %2, %0;" : "+l"(d) : "l"(a), "l"(b))
#define PACK2(d, lo, hi) asm("mov.b64 %0, {%1, %2};" : "=l"(d) : "r"(lo), "r"(hi))
#define UNPK2(lo, hi, s) asm("mov.b64 {%0, %1}, %2;" : "=r"(lo), "=r"(hi) : "l"(s))

typedef unsigned long long u64;
typedef unsigned int       u32;

// -------- device scratch (no allocations allowed) --------
__device__ float          g_Iext[(size_t)T_STEPS * BATCH * NH];   // 131 MB
__device__ unsigned short g_spk16[2][BATCH * NH];                 // bf16 spikes
__device__ float          g_rate[BATCH * NH];
__device__ unsigned int   g_bar;
__device__ unsigned int   g_mdone[MBLKS];                         // 8 = m-block ready

__global__ void init_kernel() {
    int i = threadIdx.x;
    if (i == 0) g_bar = 0u;
    for (; i < MBLKS; i += blockDim.x) g_mdone[i] = 0u;
}

__device__ __forceinline__ u32 ld_acq(const unsigned int* p) {
    u32 v;
    asm volatile("ld.global.acquire.gpu.u32 %0, [%1];" : "=r"(v) : "l"(p));
    return v;
}

#define RSTAGE(M, NHALF)                                                        \
    if (ln & (M)) {                                                             \
        _Pragma("unroll")                                                       \
        for (int i = 0; i < (NHALF); i++) {                                     \
            float tmp = a[i]; a[i] = a[i + (NHALF)]; a[i + (NHALF)] = tmp;      \
        }                                                                       \
    }                                                                           \
    _Pragma("unroll")                                                           \
    for (int i = 0; i < (NHALF); i++)                                           \
        a[i] += __shfl_xor_sync(0xffffffffu, a[i + (NHALF)], (M));

// ==================== fused kernel ====================
__global__ __launch_bounds__(256, 2) void fused_kernel(const float* __restrict__ x,
                                                       const float* __restrict__ Win,
                                                       const float* __restrict__ Wrec) {
    extern __shared__ float smf[];
    const int tid = threadIdx.x;

    if (blockIdx.x >= NBLK) {
        // ================= GEMM path (R4-exact math) =================
        const int gb = blockIdx.x - NBLK;
        const int m0 = (gb >> 3) * BM;
        const int n0 = (gb & 7) * BN;
        float* As = smf;           // [BK][BM]
        float* Bs = smf + BK * BM; // [BK][BN]

        const int lr = tid >> 1;
        const int lc = (tid & 1) * 4;
        const int tx = tid & 15, ty = tid >> 4;
        u64 acc[8][4];
#pragma unroll
        for (int i = 0; i < 8; i++)
#pragma unroll
            for (int j = 0; j < 4; j++) acc[i][j] = 0ull;

        for (int kc = 0; kc < NI; kc += BK) {
            float4 av = *(const float4*)&x  [(size_t)(m0 + lr) * NI + kc + lc];
            float4 bv = *(const float4*)&Win[(size_t)(n0 + lr) * NI + kc + lc];
            As[(lc + 0) * BM + lr] = av.x; As[(lc + 1) * BM + lr] = av.y;
            As[(lc + 2) * BM + lr] = av.z; As[(lc + 3) * BM + lr] = av.w;
            Bs[(lc + 0) * BN + lr] = bv.x; Bs[(lc + 1) * BN + lr] = bv.y;
            Bs[(lc + 2) * BN + lr] = bv.z; Bs[(lc + 3) * BN + lr] = bv.w;
            __syncthreads();
#pragma unroll
            for (int k = 0; k < BK; k++) {
                float4 a0 = *(const float4*)&As[k * BM + ty * 8];
                float4 a1 = *(const float4*)&As[k * BM + ty * 8 + 4];
                ulonglong2 bp = *(const ulonglong2*)&Bs[k * BN + tx * 8];
                ulonglong2 bq = *(const ulonglong2*)&Bs[k * BN + tx * 8 + 4];
                float aa[8] = {a0.x, a0.y, a0.z, a0.w, a1.x, a1.y, a1.z, a1.w};
                u64 ap[8];
#pragma unroll
                for (int i = 0; i < 8; i++) {
                    u32 ab = __float_as_uint(aa[i]);
                    PACK2(ap[i], ab, ab);
                }
#pragma unroll
                for (int i = 0; i < 8; i++) {
                    FMA2(acc[i][0], ap[i], bp.x);
                    FMA2(acc[i][1], ap[i], bp.y);
                    FMA2(acc[i][2], ap[i], bq.x);
                    FMA2(acc[i][3], ap[i], bq.y);
                }
            }
            __syncthreads();
        }
#pragma unroll
        for (int i = 0; i < 8; i++) {
            float o[8];
#pragma unroll
            for (int j = 0; j < 4; j++) {
                u32 lo, hi;
                UNPK2(lo, hi, acc[i][j]);
                o[2 * j]     = __uint_as_float(lo);
                o[2 * j + 1] = __uint_as_float(hi);
            }
            float4 o0 = {o[0], o[1], o[2], o[3]};
            float4 o1 = {o[4], o[5], o[6], o[7]};
            float* dst = &g_Iext[(size_t)(m0 + ty * 8 + i) * NH + n0 + tx * 8];
            *(float4*)dst = o0;
            *(float4*)(dst + 4) = o1;
        }
        __syncthreads();
        if (tid == 0) {
            __threadfence();
            asm volatile("red.release.gpu.global.add.u32 [%0], 1;"
                         :: "l"(&g_mdone[gb >> 3]) : "memory");
        }
        return;
    }

    // ================= scan path (R4-exact math) =================
    float* wt = smf;                   // 8 x 1024 weight slice (32 KB)
    __shared__ int s_rdy;              // m-blocks known complete

    const int w  = tid >> 5;
    const int ln = tid & 31;
    const int c  = blockIdx.x;
    const int h0 = c * 8;
    const int bg = w >> 1;
    const int hg = w & 1;

    {
        const float4* src = (const float4*)(Wrec + (size_t)h0 * NH);
#pragma unroll
        for (int i = 0; i < 8; i++)
            ((float4*)wt)[tid + i * 256] = src[tid + i * 256];
    }
    // gate on first I_ext m-block
    if (tid == 0) {
        while (ld_acq(&g_mdone[0]) != 8) {}
        s_rdy = 1;
    }
    __syncthreads();

    const int b = 8 * bg + (ln >> 2);
    const int h = h0 + 4 * hg + (ln & 3);
    const float* wbase = wt + (4 * hg) * NH + 4 * ln;

    float v = V_RST, a0 = 0.f, a1 = 0.f, ref = 0.f, hs = 0.f, psc = 0.f;
    int cnt = 0;
    int rr  = 1;                        // thread0's private ready count
    int rdy = 1;
    float Iv = __ldcg(&g_Iext[(size_t)b * NH + h]);

    for (int t = 0; t < T_STEPS; t++) {
        if (t > 0) {
            const char* sp = (const char*)g_spk16[(t - 1) & 1];
            u64 acc[32];
#pragma unroll
            for (int i = 0; i < 32; i++) acc[i] = 0ull;

            uint2 s[8], sn[8];
#pragma unroll
            for (int bb = 0; bb < 8; bb++)
                s[bb] = __ldcg((const uint2*)(sp + (8 * bg + bb) * (NH * 2) + 8 * ln));

#pragma unroll
            for (int u = 0; u < 8; u++) {
                if (u < 7) {
#pragma unroll
                    for (int bb = 0; bb < 8; bb++)
                        sn[bb] = __ldcg((const uint2*)(sp + (8 * bg + bb) * (NH * 2)
                                                          + 8 * ln + 256 * (u + 1)));
                }
                u64 p0[8], p1[8];
#pragma unroll
                for (int bb = 0; bb < 8; bb++) {
                    PACK2(p0[bb], s[bb].x << 16, s[bb].x & 0xFFFF0000u);
                    PACK2(p1[bb], s[bb].y << 16, s[bb].y & 0xFFFF0000u);
                }
#pragma unroll
                for (int hh = 0; hh < 4; hh++) {
                    ulonglong2 wv = *(const ulonglong2*)(wbase + hh * NH + 128 * u);
#pragma unroll
                    for (int bb = 0; bb < 8; bb++) {
                        FMA2(acc[bb * 4 + hh], p0[bb], wv.x);
                        FMA2(acc[bb * 4 + hh], p1[bb], wv.y);
                    }
                }
#pragma unroll
                for (int bb = 0; bb < 8; bb++) s[bb] = sn[bb];
            }

            float a[32];
#pragma unroll
            for (int i = 0; i < 32; i++) {
                u32 lo, hi;
                UNPK2(lo, hi, acc[i]);
                a[i] = __uint_as_float(lo) + __uint_as_float(hi);
            }
            RSTAGE(16, 16)
            RSTAGE(8, 8)
            RSTAGE(4, 4)
            RSTAGE(2, 2)
            RSTAGE(1, 1)
            float rec = a[0];

            hs  = D_SYN * hs + rec;
            psc = D_SYN * psc + hs;
        }

        float I = Iv + psc;
        a0 *= D_A0;
        a1 *= D_A1;
        v = v + ((V_RST - v) * (1.0f / 20.0f) + (I + a0 + a1) * 0.5f);
        bool in_ref = ref > 0.0f;
        if (in_ref) v = V_RST;
        float spike = (!in_ref && v >= V_TH) ? 1.0f : 0.0f;
        unsigned short s16;
        if (spike > 0.0f) {
            v = V_RST; a0 += 1.0f; a1 -= 2.0f; ref = 2.0f; cnt++;
            s16 = 0x3F80;
        } else {
            ref = fmaxf(ref - 1.0f, 0.0f);
            s16 = 0;
        }
        g_spk16[t & 1][b * NH + h] = s16;

        // prefetch I_ext(t+1) early when its m-block is known ready
        const int  tn    = t + 1;
        const int  nb    = tn >> 2;
        const bool last  = (tn >= T_STEPS);
        const bool early = last || (nb < rdy);
        if (!last && early)
            Iv = __ldcg(&g_Iext[((size_t)tn * BATCH + b) * NH + h]);

        // grid barrier + ready-count advance
        __syncthreads();
        if (tid == 0) {
            __threadfence();
            atomicAdd(&g_bar, 1u);
            while (rr < MBLKS && ld_acq(&g_mdone[rr]) == 8) rr++;
            const unsigned target = (unsigned)(t + 1) * NBLK;
            while (ld_acq(&g_bar) < target) {}
            s_rdy = rr;
        }
        __syncthreads();
        rdy = s_rdy;

        if (!last && !early) {
            if (tid == 0) {
                while (ld_acq(&g_mdone[nb]) != 8) {}
            }
            __syncthreads();
            Iv = __ldcg(&g_Iext[((size_t)tn * BATCH + b) * NH + h]);
        }
    }
    g_rate[b * NH + h] = (float)cnt * 0.001f;
}

// -------- Phase C --------
__global__ __launch_bounds__(256) void out_kernel(const float* __restrict__ Wout,
                                                  float* __restrict__ out) {
    int gw   = (blockIdx.x * blockDim.x + threadIdx.x) >> 5;
    int lane = threadIdx.x & 31;
    int b = gw >> 8;
    int o = gw & 255;
    const float* r = &g_rate[b * NH];
    const float* wp = &Wout[(size_t)o * NH];
    float s = 0.f;
    for (int hh = lane; hh < NH; hh += 32) s += r[hh] * wp[hh];
#pragma unroll
    for (int off = 16; off; off >>= 1) s += __shfl_down_sync(0xffffffffu, s, off);
    if (lane == 0) out[b * NO + o] = s;
}

// -------- launch --------
extern "C" void kernel_launch(void* const* d_in, const int* in_sizes, int n_in,
                              void* d_out, int out_size) {
    const float* x = nullptr;
    const float* W_in = nullptr;
    const float* W_rec = nullptr;
    const float* W_out = nullptr;
    for (int i = 0; i < n_in; i++) {
        switch (in_sizes[i]) {
            case T_STEPS * BATCH * NI: x     = (const float*)d_in[i]; break;
            case NH * NI:              W_in  = (const float*)d_in[i]; break;
            case NH * NH:              W_rec = (const float*)d_in[i]; break;
            case NO * NH:              W_out = (const float*)d_in[i]; break;
        }
    }
    float* out = (float*)d_out;

    init_kernel<<<1, 256>>>();

    // 128 scan CTAs + 2000 gemm CTAs, 32 KB dynamic smem each
    fused_kernel<<<NBLK + GBLKS, 256, 8 * NH * 4>>>(x, W_in, W_rec);

    out_kernel<<<(BATCH * NO * 32) / 256, 256>>>(W_out, out);
}

// round 13
// speedup vs baseline: 1.2921x; 1.2921x over previous
#include <cuda_runtime.h>
#include <cstdint>

// MinimalRSNN: GLIF3 + AlphaPSC recurrent SNN.
//   Phase A: I_ext = x @ W_in^T  (fp32 SGEMM, 128x128x8, f32x2 packed FMA)
//   Phase B: persistent 1000-step scan, 128 CTAs (R4-exact inner math)
//            barrier arrive = red.release (no full MEMBAR.GPU)
//   Phase C: out = spike_rate @ W_out^T
// Launch order: harness poisons occupy global idx 0,1; mine are
//   init(2), gemm(3), init(4), scan(5), out(6)  ->  ncu -s 5 -c 1 captures scan.

#define T_STEPS 1000
#define BATCH   32
#define NI      512
#define NH      1024
#define NO      256

#define V_TH   (-45.0f)
#define V_RST  (-60.0f)
#define D_SYN  0.8187307530779818f
#define D_A0   0.9048374180359595f
#define D_A1   0.8187307530779818f

#define NBLK   128

#define FMA2(d, a, b)  asm("fma.rn.f32x2 %0, %1, %2, %0;" : "+l"(d) : "l"(a), "l"(b))
#define PACK2(d, lo, hi) asm("mov.b64 %0, {%1, %2};" : "=l"(d) : "r"(lo), "r"(hi))
#define UNPK2(lo, hi, s) asm("mov.b64 {%0, %1}, %2;" : "=r"(lo), "=r"(hi) : "l"(s))

typedef unsigned long long u64;
typedef unsigned int       u32;

// -------- device scratch (no allocations allowed) --------
__device__ float          g_Iext[(size_t)T_STEPS * BATCH * NH];   // 131 MB
__device__ unsigned short g_spk16[2][BATCH * NH];                 // bf16 spikes
__device__ float          g_rate[BATCH * NH];
__device__ unsigned int   g_bar;

__global__ void init_kernel() { if (threadIdx.x == 0) g_bar = 0u; }

// -------- Phase A: C[M,N] = A[M,K] * B[N,K]^T (fp32, f32x2 inner) --------
#define BM 128
#define BN 128
#define BK 8
__global__ __launch_bounds__(256, 2) void gemm_in_kernel(const float* __restrict__ A,
                                                         const float* __restrict__ Bm) {
    __shared__ float As[BK][BM];
    __shared__ float Bs[BK][BN];
    const int tid = threadIdx.x;
    const int m0 = blockIdx.y * BM, n0 = blockIdx.x * BN;
    const int lr = tid >> 1;
    const int lc = (tid & 1) * 4;
    const int tx = tid & 15, ty = tid >> 4;
    u64 acc[8][4];
#pragma unroll
    for (int i = 0; i < 8; i++)
#pragma unroll
        for (int j = 0; j < 4; j++) acc[i][j] = 0ull;

    for (int kc = 0; kc < NI; kc += BK) {
        float4 av = *(const float4*)&A [(size_t)(m0 + lr) * NI + kc + lc];
        float4 bv = *(const float4*)&Bm[(size_t)(n0 + lr) * NI + kc + lc];
        As[lc + 0][lr] = av.x; As[lc + 1][lr] = av.y;
        As[lc + 2][lr] = av.z; As[lc + 3][lr] = av.w;
        Bs[lc + 0][lr] = bv.x; Bs[lc + 1][lr] = bv.y;
        Bs[lc + 2][lr] = bv.z; Bs[lc + 3][lr] = bv.w;
        __syncthreads();
#pragma unroll
        for (int k = 0; k < BK; k++) {
            float4 a0 = *(const float4*)&As[k][ty * 8];
            float4 a1 = *(const float4*)&As[k][ty * 8 + 4];
            ulonglong2 bp = *(const ulonglong2*)&Bs[k][tx * 8];
            ulonglong2 bq = *(const ulonglong2*)&Bs[k][tx * 8 + 4];
            float aa[8] = {a0.x, a0.y, a0.z, a0.w, a1.x, a1.y, a1.z, a1.w};
            u64 ap[8];
#pragma unroll
            for (int i = 0; i < 8; i++) {
                u32 ab = __float_as_uint(aa[i]);
                PACK2(ap[i], ab, ab);
            }
#pragma unroll
            for (int i = 0; i < 8; i++) {
                FMA2(acc[i][0], ap[i], bp.x);
                FMA2(acc[i][1], ap[i], bp.y);
                FMA2(acc[i][2], ap[i], bq.x);
                FMA2(acc[i][3], ap[i], bq.y);
            }
        }
        __syncthreads();
    }
#pragma unroll
    for (int i = 0; i < 8; i++) {
        float o[8];
#pragma unroll
        for (int j = 0; j < 4; j++) {
            u32 lo, hi;
            UNPK2(lo, hi, acc[i][j]);
            o[2 * j]     = __uint_as_float(lo);
            o[2 * j + 1] = __uint_as_float(hi);
        }
        float4 o0 = {o[0], o[1], o[2], o[3]};
        float4 o1 = {o[4], o[5], o[6], o[7]};
        float* dst = &g_Iext[(size_t)(m0 + ty * 8 + i) * NH + n0 + tx * 8];
        *(float4*)dst = o0;
        *(float4*)(dst + 4) = o1;
    }
}

// -------- grid barrier: release-reduction arrive, acquire poll --------
__device__ __forceinline__ void grid_sync(int step) {
    __syncthreads();
    if (threadIdx.x == 0) {
        asm volatile("red.release.gpu.global.add.u32 [%0], 1;"
                     :: "l"(&g_bar) : "memory");
        const unsigned target = (unsigned)(step + 1) * NBLK;
        unsigned cur;
        do {
            asm volatile("ld.global.acquire.gpu.u32 %0, [%1];" : "=r"(cur) : "l"(&g_bar));
        } while (cur < target);
    }
    __syncthreads();
}

#define RSTAGE(M, NHALF)                                                        \
    if (ln & (M)) {                                                             \
        _Pragma("unroll")                                                       \
        for (int i = 0; i < (NHALF); i++) {                                     \
            float tmp = a[i]; a[i] = a[i + (NHALF)]; a[i + (NHALF)] = tmp;      \
        }                                                                       \
    }                                                                           \
    _Pragma("unroll")                                                           \
    for (int i = 0; i < (NHALF); i++)                                           \
        a[i] += __shfl_xor_sync(0xffffffffu, a[i + (NHALF)], (M));

// -------- Phase B: persistent scan (R4-exact) --------
__global__ __launch_bounds__(256, 1) void scan_kernel(const float* __restrict__ Wrec) {
    __shared__ float wt[8 * NH];

    const int tid = threadIdx.x;
    const int w  = tid >> 5;
    const int ln = tid & 31;
    const int c  = blockIdx.x;
    const int h0 = c * 8;
    const int bg = w >> 1;
    const int hg = w & 1;

    {
        const float4* src = (const float4*)(Wrec + (size_t)h0 * NH);
#pragma unroll
        for (int i = 0; i < 8; i++)
            ((float4*)wt)[tid + i * 256] = src[tid + i * 256];
    }
    __syncthreads();

    const int b = 8 * bg + (ln >> 2);
    const int h = h0 + 4 * hg + (ln & 3);
    const float* wbase = wt + (4 * hg) * NH + 4 * ln;

    float v = V_RST, a0 = 0.f, a1 = 0.f, ref = 0.f, hs = 0.f, psc = 0.f;
    int cnt = 0;
    float Iv = __ldcg(&g_Iext[(size_t)b * NH + h]);

    for (int t = 0; t < T_STEPS; t++) {
        if (t > 0) {
            const char* sp = (const char*)g_spk16[(t - 1) & 1];
            u64 acc[32];
#pragma unroll
            for (int i = 0; i < 32; i++) acc[i] = 0ull;

            uint2 s[8], sn[8];
#pragma unroll
            for (int bb = 0; bb < 8; bb++)
                s[bb] = __ldcg((const uint2*)(sp + (8 * bg + bb) * (NH * 2) + 8 * ln));

#pragma unroll
            for (int u = 0; u < 8; u++) {
                if (u < 7) {
#pragma unroll
                    for (int bb = 0; bb < 8; bb++)
                        sn[bb] = __ldcg((const uint2*)(sp + (8 * bg + bb) * (NH * 2)
                                                          + 8 * ln + 256 * (u + 1)));
                }
                u64 p0[8], p1[8];
#pragma unroll
                for (int bb = 0; bb < 8; bb++) {
                    PACK2(p0[bb], s[bb].x << 16, s[bb].x & 0xFFFF0000u);
                    PACK2(p1[bb], s[bb].y << 16, s[bb].y & 0xFFFF0000u);
                }
#pragma unroll
                for (int hh = 0; hh < 4; hh++) {
                    ulonglong2 wv = *(const ulonglong2*)(wbase + hh * NH + 128 * u);
#pragma unroll
                    for (int bb = 0; bb < 8; bb++) {
                        FMA2(acc[bb * 4 + hh], p0[bb], wv.x);
                        FMA2(acc[bb * 4 + hh], p1[bb], wv.y);
                    }
                }
#pragma unroll
                for (int bb = 0; bb < 8; bb++) s[bb] = sn[bb];
            }

            float a[32];
#pragma unroll
            for (int i = 0; i < 32; i++) {
                u32 lo, hi;
                UNPK2(lo, hi, acc[i]);
                a[i] = __uint_as_float(lo) + __uint_as_float(hi);
            }
            RSTAGE(16, 16)
            RSTAGE(8, 8)
            RSTAGE(4, 4)
            RSTAGE(2, 2)
            RSTAGE(1, 1)
            float rec = a[0];

            hs  = D_SYN * hs + rec;
            psc = D_SYN * psc + hs;
        }

        float I = Iv + psc;
        a0 *= D_A0;
        a1 *= D_A1;
        v = v + ((V_RST - v) * (1.0f / 20.0f) + (I + a0 + a1) * 0.5f);
        bool in_ref = ref > 0.0f;
        if (in_ref) v = V_RST;
        float spike = (!in_ref && v >= V_TH) ? 1.0f : 0.0f;
        unsigned short s16;
        if (spike > 0.0f) {
            v = V_RST; a0 += 1.0f; a1 -= 2.0f; ref = 2.0f; cnt++;
            s16 = 0x3F80;
        } else {
            ref = fmaxf(ref - 1.0f, 0.0f);
            s16 = 0;
        }
        g_spk16[t & 1][b * NH + h] = s16;

        int tn = (t < T_STEPS - 1) ? t + 1 : t;
        Iv = __ldcg(&g_Iext[((size_t)tn * BATCH + b) * NH + h]);

        grid_sync(t);
    }
    g_rate[b * NH + h] = (float)cnt * 0.001f;
}

// -------- Phase C --------
__global__ __launch_bounds__(256) void out_kernel(const float* __restrict__ Wout,
                                                  float* __restrict__ out) {
    int gw   = (blockIdx.x * blockDim.x + threadIdx.x) >> 5;
    int lane = threadIdx.x & 31;
    int b = gw >> 8;
    int o = gw & 255;
    const float* r = &g_rate[b * NH];
    const float* wp = &Wout[(size_t)o * NH];
    float s = 0.f;
    for (int hh = lane; hh < NH; hh += 32) s += r[hh] * wp[hh];
#pragma unroll
    for (int off = 16; off; off >>= 1) s += __shfl_down_sync(0xffffffffu, s, off);
    if (lane == 0) out[b * NO + o] = s;
}

// -------- launch --------
extern "C" void kernel_launch(void* const* d_in, const int* in_sizes, int n_in,
                              void* d_out, int out_size) {
    const float* x = nullptr;
    const float* W_in = nullptr;
    const float* W_rec = nullptr;
    const float* W_out = nullptr;
    for (int i = 0; i < n_in; i++) {
        switch (in_sizes[i]) {
            case T_STEPS * BATCH * NI: x     = (const float*)d_in[i]; break;
            case NH * NI:              W_in  = (const float*)d_in[i]; break;
            case NH * NH:              W_rec = (const float*)d_in[i]; break;
            case NO * NH:              W_out = (const float*)d_in[i]; break;
        }
    }
    float* out = (float*)d_out;

    // harness launches 2 poison kernels first (global idx 0,1)
    init_kernel<<<1, 32>>>();                    // global 2

    dim3 g1(NH / BN, (T_STEPS * BATCH) / BM);    // (8, 250)
    gemm_in_kernel<<<g1, 256>>>(x, W_in);        // global 3

    init_kernel<<<1, 32>>>();                    // global 4

    scan_kernel<<<NBLK, 256>>>(W_rec);           // global 5  <- ncu -s 5 -c 1

    out_kernel<<<(BATCH * NO * 32) / 256, 256>>>(W_out, out);   // global 6
}

// round 14
// speedup vs baseline: 1.3307x; 1.0299x over previous
#include <cuda_runtime.h>
#include <cstdint>

// MinimalRSNN: GLIF3 + AlphaPSC recurrent SNN.
//   Phase A: I_ext = x @ W_in^T  (fp32 SGEMM, 128x128x8, f32x2 packed FMA)
//   Phase B: persistent 1000-step scan, 256 CTAs x 128 thr, 2 CTAs/SM
//            (decoupled CTA pair hides barrier + L2 latency; per-warp math
//             bit-identical to the R4 champion)
//   Phase C: out = spike_rate @ W_out^T
// Launch order: harness poisons = global idx 0,1; mine: init(2), gemm(3),
//   init(4), scan(5), out(6)  ->  ncu -s 5 -c 1 captures the scan.

#define T_STEPS 1000
#define BATCH   32
#define NI      512
#define NH      1024
#define NO      256

#define V_TH   (-45.0f)
#define V_RST  (-60.0f)
#define D_SYN  0.8187307530779818f
#define D_A0   0.9048374180359595f
#define D_A1   0.8187307530779818f

#define NBLK   256      // scan CTAs (2 per SM on 128 SMs)

#define FMA2(d, a, b)  asm("fma.rn.f32x2 %0, %1, %2, %0;" : "+l"(d) : "l"(a), "l"(b))
#define PACK2(d, lo, hi) asm("mov.b64 %0, {%1, %2};" : "=l"(d) : "r"(lo), "r"(hi))
#define UNPK2(lo, hi, s) asm("mov.b64 {%0, %1}, %2;" : "=r"(lo), "=r"(hi) : "l"(s))

typedef unsigned long long u64;
typedef unsigned int       u32;

// -------- device scratch (no allocations allowed) --------
__device__ float          g_Iext[(size_t)T_STEPS * BATCH * NH];   // 131 MB
__device__ unsigned short g_spk16[2][BATCH * NH];                 // bf16 spikes
__device__ float          g_rate[BATCH * NH];
__device__ unsigned int   g_bar;

__global__ void init_kernel() { if (threadIdx.x == 0) g_bar = 0u; }

// -------- Phase A: C[M,N] = A[M,K] * B[N,K]^T (fp32, f32x2 inner) --------
#define BM 128
#define BN 128
#define BK 8
__global__ __launch_bounds__(256, 2) void gemm_in_kernel(const float* __restrict__ A,
                                                         const float* __restrict__ Bm) {
    __shared__ float As[BK][BM];
    __shared__ float Bs[BK][BN];
    const int tid = threadIdx.x;
    const int m0 = blockIdx.y * BM, n0 = blockIdx.x * BN;
    const int lr = tid >> 1;
    const int lc = (tid & 1) * 4;
    const int tx = tid & 15, ty = tid >> 4;
    u64 acc[8][4];
#pragma unroll
    for (int i = 0; i < 8; i++)
#pragma unroll
        for (int j = 0; j < 4; j++) acc[i][j] = 0ull;

    for (int kc = 0; kc < NI; kc += BK) {
        float4 av = *(const float4*)&A [(size_t)(m0 + lr) * NI + kc + lc];
        float4 bv = *(const float4*)&Bm[(size_t)(n0 + lr) * NI + kc + lc];
        As[lc + 0][lr] = av.x; As[lc + 1][lr] = av.y;
        As[lc + 2][lr] = av.z; As[lc + 3][lr] = av.w;
        Bs[lc + 0][lr] = bv.x; Bs[lc + 1][lr] = bv.y;
        Bs[lc + 2][lr] = bv.z; Bs[lc + 3][lr] = bv.w;
        __syncthreads();
#pragma unroll
        for (int k = 0; k < BK; k++) {
            float4 a0 = *(const float4*)&As[k][ty * 8];
            float4 a1 = *(const float4*)&As[k][ty * 8 + 4];
            ulonglong2 bp = *(const ulonglong2*)&Bs[k][tx * 8];
            ulonglong2 bq = *(const ulonglong2*)&Bs[k][tx * 8 + 4];
            float aa[8] = {a0.x, a0.y, a0.z, a0.w, a1.x, a1.y, a1.z, a1.w};
            u64 ap[8];
#pragma unroll
            for (int i = 0; i < 8; i++) {
                u32 ab = __float_as_uint(aa[i]);
                PACK2(ap[i], ab, ab);
            }
#pragma unroll
            for (int i = 0; i < 8; i++) {
                FMA2(acc[i][0], ap[i], bp.x);
                FMA2(acc[i][1], ap[i], bp.y);
                FMA2(acc[i][2], ap[i], bq.x);
                FMA2(acc[i][3], ap[i], bq.y);
            }
        }
        __syncthreads();
    }
#pragma unroll
    for (int i = 0; i < 8; i++) {
        float o[8];
#pragma unroll
        for (int j = 0; j < 4; j++) {
            u32 lo, hi;
            UNPK2(lo, hi, acc[i][j]);
            o[2 * j]     = __uint_as_float(lo);
            o[2 * j + 1] = __uint_as_float(hi);
        }
        float4 o0 = {o[0], o[1], o[2], o[3]};
        float4 o1 = {o[4], o[5], o[6], o[7]};
        float* dst = &g_Iext[(size_t)(m0 + ty * 8 + i) * NH + n0 + tx * 8];
        *(float4*)dst = o0;
        *(float4*)(dst + 4) = o1;
    }
}

// -------- grid barrier: release arrive, acquire poll (256 CTAs) --------
__device__ __forceinline__ void grid_sync(int step) {
    __syncthreads();
    if (threadIdx.x == 0) {
        asm volatile("red.release.gpu.global.add.u32 [%0], 1;"
                     :: "l"(&g_bar) : "memory");
        const unsigned target = (unsigned)(step + 1) * NBLK;
        unsigned cur;
        do {
            asm volatile("ld.global.acquire.gpu.u32 %0, [%1];" : "=r"(cur) : "l"(&g_bar));
        } while (cur < target);
    }
    __syncthreads();
}

#define RSTAGE(M, NHALF)                                                        \
    if (ln & (M)) {                                                             \
        _Pragma("unroll")                                                       \
        for (int i = 0; i < (NHALF); i++) {                                     \
            float tmp = a[i]; a[i] = a[i + (NHALF)]; a[i + (NHALF)] = tmp;      \
        }                                                                       \
    }                                                                           \
    _Pragma("unroll")                                                           \
    for (int i = 0; i < (NHALF); i++)                                           \
        a[i] += __shfl_xor_sync(0xffffffffu, a[i + (NHALF)], (M));

// -------- Phase B: persistent scan, 256 CTAs x 128 threads (2/SM) --------
// CTA c owns h in [4c, 4c+4), warp w owns batches [8w, 8w+8).
// Per-warp math is bit-identical to R4 (hg became the CTA split).
__global__ __launch_bounds__(128, 2) void scan_kernel(const float* __restrict__ Wrec) {
    __shared__ float wt[4 * NH];       // 16 KB: this CTA's 4 W_rec rows

    const int tid = threadIdx.x;
    const int w  = tid >> 5;           // 0..3  -> batches [8w, 8w+8)
    const int ln = tid & 31;
    const int c  = blockIdx.x;
    const int h0 = c * 4;

    // preload weights: 1024 float4 over 128 threads
    {
        const float4* src = (const float4*)(Wrec + (size_t)h0 * NH);
#pragma unroll
        for (int i = 0; i < 8; i++)
            ((float4*)wt)[tid + i * 128] = src[tid + i * 128];
    }
    __syncthreads();

    // lane ownership: output index ln = bb*4 + hh
    const int b = 8 * w + (ln >> 2);
    const int h = h0 + (ln & 3);
    const float* wbase = wt + 4 * ln;             // + hh*NH + 128*u

    float v = V_RST, a0 = 0.f, a1 = 0.f, ref = 0.f, hs = 0.f, psc = 0.f;
    int cnt = 0;
    float Iv = __ldcg(&g_Iext[(size_t)b * NH + h]);

    for (int t = 0; t < T_STEPS; t++) {
        if (t > 0) {
            const char* sp = (const char*)g_spk16[(t - 1) & 1];
            u64 acc[32];
#pragma unroll
            for (int i = 0; i < 32; i++) acc[i] = 0ull;

            uint2 s[8], sn[8];
#pragma unroll
            for (int bb = 0; bb < 8; bb++)
                s[bb] = __ldcg((const uint2*)(sp + (8 * w + bb) * (NH * 2) + 8 * ln));

#pragma unroll
            for (int u = 0; u < 8; u++) {
                if (u < 7) {
#pragma unroll
                    for (int bb = 0; bb < 8; bb++)
                        sn[bb] = __ldcg((const uint2*)(sp + (8 * w + bb) * (NH * 2)
                                                          + 8 * ln + 256 * (u + 1)));
                }
                u64 p0[8], p1[8];
#pragma unroll
                for (int bb = 0; bb < 8; bb++) {
                    PACK2(p0[bb], s[bb].x << 16, s[bb].x & 0xFFFF0000u);
                    PACK2(p1[bb], s[bb].y << 16, s[bb].y & 0xFFFF0000u);
                }
#pragma unroll
                for (int hh = 0; hh < 4; hh++) {
                    ulonglong2 wv = *(const ulonglong2*)(wbase + hh * NH + 128 * u);
#pragma unroll
                    for (int bb = 0; bb < 8; bb++) {
                        FMA2(acc[bb * 4 + hh], p0[bb], wv.x);
                        FMA2(acc[bb * 4 + hh], p1[bb], wv.y);
                    }
                }
#pragma unroll
                for (int bb = 0; bb < 8; bb++) s[bb] = sn[bb];
            }

            float a[32];
#pragma unroll
            for (int i = 0; i < 32; i++) {
                u32 lo, hi;
                UNPK2(lo, hi, acc[i]);
                a[i] = __uint_as_float(lo) + __uint_as_float(hi);
            }
            RSTAGE(16, 16)
            RSTAGE(8, 8)
            RSTAGE(4, 4)
            RSTAGE(2, 2)
            RSTAGE(1, 1)
            float rec = a[0];

            hs  = D_SYN * hs + rec;
            psc = D_SYN * psc + hs;
        }

        float I = Iv + psc;
        a0 *= D_A0;
        a1 *= D_A1;
        v = v + ((V_RST - v) * (1.0f / 20.0f) + (I + a0 + a1) * 0.5f);
        bool in_ref = ref > 0.0f;
        if (in_ref) v = V_RST;
        float spike = (!in_ref && v >= V_TH) ? 1.0f : 0.0f;
        unsigned short s16;
        if (spike > 0.0f) {
            v = V_RST; a0 += 1.0f; a1 -= 2.0f; ref = 2.0f; cnt++;
            s16 = 0x3F80;
        } else {
            ref = fmaxf(ref - 1.0f, 0.0f);
            s16 = 0;
        }
        g_spk16[t & 1][b * NH + h] = s16;

        int tn = (t < T_STEPS - 1) ? t + 1 : t;
        Iv = __ldcg(&g_Iext[((size_t)tn * BATCH + b) * NH + h]);

        grid_sync(t);
    }
    g_rate[b * NH + h] = (float)cnt * 0.001f;
}

// -------- Phase C --------
__global__ __launch_bounds__(256) void out_kernel(const float* __restrict__ Wout,
                                                  float* __restrict__ out) {
    int gw   = (blockIdx.x * blockDim.x + threadIdx.x) >> 5;
    int lane = threadIdx.x & 31;
    int b = gw >> 8;
    int o = gw & 255;
    const float* r = &g_rate[b * NH];
    const float* wp = &Wout[(size_t)o * NH];
    float s = 0.f;
    for (int hh = lane; hh < NH; hh += 32) s += r[hh] * wp[hh];
#pragma unroll
    for (int off = 16; off; off >>= 1) s += __shfl_down_sync(0xffffffffu, s, off);
    if (lane == 0) out[b * NO + o] = s;
}

// -------- launch --------
extern "C" void kernel_launch(void* const* d_in, const int* in_sizes, int n_in,
                              void* d_out, int out_size) {
    const float* x = nullptr;
    const float* W_in = nullptr;
    const float* W_rec = nullptr;
    const float* W_out = nullptr;
    for (int i = 0; i < n_in; i++) {
        switch (in_sizes[i]) {
            case T_STEPS * BATCH * NI: x     = (const float*)d_in[i]; break;
            case NH * NI:              W_in  = (const float*)d_in[i]; break;
            case NH * NH:              W_rec = (const float*)d_in[i]; break;
            case NO * NH:              W_out = (const float*)d_in[i]; break;
        }
    }
    float* out = (float*)d_out;

    // harness poisons occupy global idx 0,1
    init_kernel<<<1, 32>>>();                    // global 2

    dim3 g1(NH / BN, (T_STEPS * BATCH) / BM);    // (8, 250)
    gemm_in_kernel<<<g1, 256>>>(x, W_in);        // global 3

    init_kernel<<<1, 32>>>();                    // global 4

    scan_kernel<<<NBLK, 128>>>(W_rec);           // global 5  <- ncu -s 5 -c 1

    out_kernel<<<(BATCH * NO * 32) / 256, 256>>>(W_out, out);   // global 6
}

// round 15
// speedup vs baseline: 1.3504x; 1.0148x over previous
#include <cuda_runtime.h>
#include <cstdint>

// MinimalRSNN: GLIF3 + AlphaPSC recurrent SNN.
//   Phase A: I_ext = x @ W_in^T  (fp32 SGEMM, 128x128x8, f32x2 FMA,
//            register-prefetch + double-buffered smem, 1 sync/chunk)
//   Phase B: persistent 1000-step scan, 256 CTAs x 128 thr, 2 CTAs/SM
//            float spike transport (no pack ALU), math bit-exact to R14
//   Phase C: out = spike_rate @ W_out^T
// Launch order: harness poisons = global idx 0,1; mine: init(2), gemm(3),
//   init(4), scan(5), out(6)  ->  ncu -s 5 -c 1 captures the scan.

#define T_STEPS 1000
#define BATCH   32
#define NI      512
#define NH      1024
#define NO      256

#define V_TH   (-45.0f)
#define V_RST  (-60.0f)
#define D_SYN  0.8187307530779818f
#define D_A0   0.9048374180359595f
#define D_A1   0.8187307530779818f

#define NBLK   256      // scan CTAs (2 per SM)

#define FMA2(d, a, b)  asm("fma.rn.f32x2 %0, %1, %2, %0;" : "+l"(d) : "l"(a), "l"(b))
#define PACK2(d, lo, hi) asm("mov.b64 %0, {%1, %2};" : "=l"(d) : "r"(lo), "r"(hi))
#define UNPK2(lo, hi, s) asm("mov.b64 {%0, %1}, %2;" : "=r"(lo), "=r"(hi) : "l"(s))

typedef unsigned long long u64;
typedef unsigned int       u32;

// -------- device scratch (no allocations allowed) --------
__device__ float        g_Iext[(size_t)T_STEPS * BATCH * NH];   // 131 MB
__device__ float        g_spkf[2][BATCH * NH];                  // float spikes
__device__ float        g_rate[BATCH * NH];
__device__ unsigned int g_bar;

__global__ void init_kernel() { if (threadIdx.x == 0) g_bar = 0u; }

// -------- Phase A: C[M,N] = A[M,K] * B[N,K]^T (pipelined fp32) --------
#define BM 128
#define BN 128
#define BK 8
#define NCHUNK (NI / BK)    // 64
__global__ __launch_bounds__(256, 2) void gemm_in_kernel(const float* __restrict__ A,
                                                         const float* __restrict__ Bm) {
    __shared__ float As[2][BK][BM];
    __shared__ float Bs[2][BK][BN];
    const int tid = threadIdx.x;
    const int m0 = blockIdx.y * BM, n0 = blockIdx.x * BN;
    const int lr = tid >> 1;
    const int lc = (tid & 1) * 4;
    const int tx = tid & 15, ty = tid >> 4;
    u64 acc[8][4];
#pragma unroll
    for (int i = 0; i < 8; i++)
#pragma unroll
        for (int j = 0; j < 4; j++) acc[i][j] = 0ull;

    // prologue: stage chunk 0
    {
        float4 av = *(const float4*)&A [(size_t)(m0 + lr) * NI + lc];
        float4 bv = *(const float4*)&Bm[(size_t)(n0 + lr) * NI + lc];
        As[0][lc + 0][lr] = av.x; As[0][lc + 1][lr] = av.y;
        As[0][lc + 2][lr] = av.z; As[0][lc + 3][lr] = av.w;
        Bs[0][lc + 0][lr] = bv.x; Bs[0][lc + 1][lr] = bv.y;
        Bs[0][lc + 2][lr] = bv.z; Bs[0][lc + 3][lr] = bv.w;
    }
    __syncthreads();

    for (int kc = 0; kc < NCHUNK; kc++) {
        const int buf = kc & 1;
        float4 avn, bvn;
        if (kc + 1 < NCHUNK) {
            avn = *(const float4*)&A [(size_t)(m0 + lr) * NI + (kc + 1) * BK + lc];
            bvn = *(const float4*)&Bm[(size_t)(n0 + lr) * NI + (kc + 1) * BK + lc];
        }
#pragma unroll
        for (int k = 0; k < BK; k++) {
            float4 a0 = *(const float4*)&As[buf][k][ty * 8];
            float4 a1 = *(const float4*)&As[buf][k][ty * 8 + 4];
            ulonglong2 bp = *(const ulonglong2*)&Bs[buf][k][tx * 8];
            ulonglong2 bq = *(const ulonglong2*)&Bs[buf][k][tx * 8 + 4];
            float aa[8] = {a0.x, a0.y, a0.z, a0.w, a1.x, a1.y, a1.z, a1.w};
            u64 ap[8];
#pragma unroll
            for (int i = 0; i < 8; i++) {
                u32 ab = __float_as_uint(aa[i]);
                PACK2(ap[i], ab, ab);
            }
#pragma unroll
            for (int i = 0; i < 8; i++) {
                FMA2(acc[i][0], ap[i], bp.x);
                FMA2(acc[i][1], ap[i], bp.y);
                FMA2(acc[i][2], ap[i], bq.x);
                FMA2(acc[i][3], ap[i], bq.y);
            }
        }
        if (kc + 1 < NCHUNK) {
            const int nb = buf ^ 1;
            As[nb][lc + 0][lr] = avn.x; As[nb][lc + 1][lr] = avn.y;
            As[nb][lc + 2][lr] = avn.z; As[nb][lc + 3][lr] = avn.w;
            Bs[nb][lc + 0][lr] = bvn.x; Bs[nb][lc + 1][lr] = bvn.y;
            Bs[nb][lc + 2][lr] = bvn.z; Bs[nb][lc + 3][lr] = bvn.w;
            __syncthreads();
        }
    }
#pragma unroll
    for (int i = 0; i < 8; i++) {
        float o[8];
#pragma unroll
        for (int j = 0; j < 4; j++) {
            u32 lo, hi;
            UNPK2(lo, hi, acc[i][j]);
            o[2 * j]     = __uint_as_float(lo);
            o[2 * j + 1] = __uint_as_float(hi);
        }
        float4 o0 = {o[0], o[1], o[2], o[3]};
        float4 o1 = {o[4], o[5], o[6], o[7]};
        float* dst = &g_Iext[(size_t)(m0 + ty * 8 + i) * NH + n0 + tx * 8];
        *(float4*)dst = o0;
        *(float4*)(dst + 4) = o1;
    }
}

// -------- grid barrier: release arrive, acquire poll --------
__device__ __forceinline__ void grid_sync(int step) {
    __syncthreads();
    if (threadIdx.x == 0) {
        asm volatile("red.release.gpu.global.add.u32 [%0], 1;"
                     :: "l"(&g_bar) : "memory");
        const unsigned target = (unsigned)(step + 1) * NBLK;
        unsigned cur;
        do {
            asm volatile("ld.global.acquire.gpu.u32 %0, [%1];" : "=r"(cur) : "l"(&g_bar));
        } while (cur < target);
    }
    __syncthreads();
}

#define RSTAGE(M, NHALF)                                                        \
    if (ln & (M)) {                                                             \
        _Pragma("unroll")                                                       \
        for (int i = 0; i < (NHALF); i++) {                                     \
            float tmp = a[i]; a[i] = a[i + (NHALF)]; a[i + (NHALF)] = tmp;      \
        }                                                                       \
    }                                                                           \
    _Pragma("unroll")                                                           \
    for (int i = 0; i < (NHALF); i++)                                           \
        a[i] += __shfl_xor_sync(0xffffffffu, a[i + (NHALF)], (M));

// -------- Phase B: persistent scan, 256 CTAs x 128 threads (2/SM) --------
// CTA c owns h in [4c, 4c+4), warp w owns batches [8w, 8w+8).
// Float spikes: float4 slice reinterpreted as 2 x u64 FMA2 operands
// (same (k,k+1) pairing as R14's bf16 -> bit-identical accumulation).
__global__ __launch_bounds__(128, 2) void scan_kernel(const float* __restrict__ Wrec) {
    __shared__ float wt[4 * NH];       // 16 KB: this CTA's 4 W_rec rows

    const int tid = threadIdx.x;
    const int w  = tid >> 5;
    const int ln = tid & 31;
    const int c  = blockIdx.x;
    const int h0 = c * 4;

    {
        const float4* src = (const float4*)(Wrec + (size_t)h0 * NH);
#pragma unroll
        for (int i = 0; i < 8; i++)
            ((float4*)wt)[tid + i * 128] = src[tid + i * 128];
    }
    __syncthreads();

    const int b = 8 * w + (ln >> 2);
    const int h = h0 + (ln & 3);
    const float* wbase = wt + 4 * ln;

    float v = V_RST, a0 = 0.f, a1 = 0.f, ref = 0.f, hs = 0.f, psc = 0.f;
    int cnt = 0;
    float Iv = __ldcg(&g_Iext[(size_t)b * NH + h]);

    for (int t = 0; t < T_STEPS; t++) {
        if (t > 0) {
            const float* sp = g_spkf[(t - 1) & 1];
            u64 acc[32];
#pragma unroll
            for (int i = 0; i < 32; i++) acc[i] = 0ull;

            // lane k-slice: floats at (b row)*NH + 4*ln + 128*u
            ulonglong2 s[8], sn[8];
#pragma unroll
            for (int bb = 0; bb < 8; bb++)
                s[bb] = __ldcg((const ulonglong2*)(sp + (8 * w + bb) * NH + 4 * ln));

#pragma unroll
            for (int u = 0; u < 8; u++) {
                if (u < 7) {
#pragma unroll
                    for (int bb = 0; bb < 8; bb++)
                        sn[bb] = __ldcg((const ulonglong2*)(sp + (8 * w + bb) * NH
                                                               + 4 * ln + 128 * (u + 1)));
                }
#pragma unroll
                for (int hh = 0; hh < 4; hh++) {
                    ulonglong2 wv = *(const ulonglong2*)(wbase + hh * NH + 128 * u);
#pragma unroll
                    for (int bb = 0; bb < 8; bb++) {
                        FMA2(acc[bb * 4 + hh], s[bb].x, wv.x);
                        FMA2(acc[bb * 4 + hh], s[bb].y, wv.y);
                    }
                }
#pragma unroll
                for (int bb = 0; bb < 8; bb++) s[bb] = sn[bb];
            }

            float a[32];
#pragma unroll
            for (int i = 0; i < 32; i++) {
                u32 lo, hi;
                UNPK2(lo, hi, acc[i]);
                a[i] = __uint_as_float(lo) + __uint_as_float(hi);
            }
            RSTAGE(16, 16)
            RSTAGE(8, 8)
            RSTAGE(4, 4)
            RSTAGE(2, 2)
            RSTAGE(1, 1)
            float rec = a[0];

            hs  = D_SYN * hs + rec;
            psc = D_SYN * psc + hs;
        }

        float I = Iv + psc;
        a0 *= D_A0;
        a1 *= D_A1;
        v = v + ((V_RST - v) * (1.0f / 20.0f) + (I + a0 + a1) * 0.5f);
        bool in_ref = ref > 0.0f;
        if (in_ref) v = V_RST;
        float spike = (!in_ref && v >= V_TH) ? 1.0f : 0.0f;
        if (spike > 0.0f) {
            v = V_RST; a0 += 1.0f; a1 -= 2.0f; ref = 2.0f; cnt++;
        } else {
            ref = fmaxf(ref - 1.0f, 0.0f);
        }
        g_spkf[t & 1][b * NH + h] = spike;

        int tn = (t < T_STEPS - 1) ? t + 1 : t;
        Iv = __ldcg(&g_Iext[((size_t)tn * BATCH + b) * NH + h]);

        grid_sync(t);
    }
    g_rate[b * NH + h] = (float)cnt * 0.001f;
}

// -------- Phase C --------
__global__ __launch_bounds__(256) void out_kernel(const float* __restrict__ Wout,
                                                  float* __restrict__ out) {
    int gw   = (blockIdx.x * blockDim.x + threadIdx.x) >> 5;
    int lane = threadIdx.x & 31;
    int b = gw >> 8;
    int o = gw & 255;
    const float* r = &g_rate[b * NH];
    const float* wp = &Wout[(size_t)o * NH];
    float s = 0.f;
    for (int hh = lane; hh < NH; hh += 32) s += r[hh] * wp[hh];
#pragma unroll
    for (int off = 16; off; off >>= 1) s += __shfl_down_sync(0xffffffffu, s, off);
    if (lane == 0) out[b * NO + o] = s;
}

// -------- launch --------
extern "C" void kernel_launch(void* const* d_in, const int* in_sizes, int n_in,
                              void* d_out, int out_size) {
    const float* x = nullptr;
    const float* W_in = nullptr;
    const float* W_rec = nullptr;
    const float* W_out = nullptr;
    for (int i = 0; i < n_in; i++) {
        switch (in_sizes[i]) {
            case T_STEPS * BATCH * NI: x     = (const float*)d_in[i]; break;
            case NH * NI:              W_in  = (const float*)d_in[i]; break;
            case NH * NH:              W_rec = (const float*)d_in[i]; break;
            case NO * NH:              W_out = (const float*)d_in[i]; break;
        }
    }
    float* out = (float*)d_out;

    // harness poisons occupy global idx 0,1
    init_kernel<<<1, 32>>>();                    // global 2

    dim3 g1(NH / BN, (T_STEPS * BATCH) / BM);    // (8, 250)
    gemm_in_kernel<<<g1, 256>>>(x, W_in);        // global 3

    init_kernel<<<1, 32>>>();                    // global 4

    scan_kernel<<<NBLK, 128>>>(W_rec);           // global 5  <- ncu -s 5 -c 1

    out_kernel<<<(BATCH * NO * 32) / 256, 256>>>(W_out, out);   // global 6
}